// round 4
// baseline (speedup 1.0000x reference)
#include <cuda_runtime.h>
#include <math.h>

#define GRID 148
#define TPB  512
#define NWARP (GRID*(TPB/32))   /* 2368 warps */
#define NT    (GRID*TPB)        /* 75776 threads */

#define HD   512
#define D2   1024
#define D4   2048
#define VV   32000
#define MQ   32
#define NP   4096
#define LL   64

// ---------------- device scratch (no allocation allowed) ----------------
__device__ __align__(16) float g_h[D2];
__device__ __align__(16) float g_hpart[GRID*D2];
__device__ __align__(16) float g_uah[D2];
__device__ __align__(16) float g_d[2][D4];
__device__ __align__(16) float g_rmax[HD];
__device__ __align__(16) float g_elog[VV];
__device__ float g_spart[2*GRID];
__device__ float g_bsum[GRID];
__device__ unsigned g_bar;

__global__ void init_bar_kernel() { g_bar = 0u; }

__device__ __forceinline__ float wredsum(float v) {
#pragma unroll
    for (int o = 16; o; o >>= 1) v += __shfl_xor_sync(0xffffffffu, v, o);
    return v;
}

// Grid-wide barrier: monotonic counter, release fence on arrive,
// acquire fence (gpu scope -> CCTL.IVALL, flushes this SM's L1D) on depart.
__device__ __forceinline__ void gsync(int phase) {
    __syncthreads();
    if (threadIdx.x == 0) {
        __threadfence();
        unsigned target = (unsigned)GRID * (unsigned)phase;
        atomicAdd(&g_bar, 1u);
        while (atomicAdd(&g_bar, 0u) < target) __nanosleep(64);
        __threadfence();
    }
    __syncthreads();
}

#define FMA4(acc, a, b) (acc) += (a).x*(b).x + (a).y*(b).y + (a).z*(b).z + (a).w*(b).w

__global__ __launch_bounds__(TPB, 1)
void decoder_kernel(const float* __restrict__ h_q,   const float* __restrict__ h_p,
                    const float* __restrict__ ans,   const float* __restrict__ v_w,
                    const float* __restrict__ w_d_w, const float* __restrict__ w_d_b,
                    const float* __restrict__ w_a_w, const float* __restrict__ u_a_w,
                    const float* __restrict__ w_r_w, const float* __restrict__ u_r_w,
                    const float* __restrict__ v_r_w, const float* __restrict__ w_o_w,
                    const float* __restrict__ gwih,  const float* __restrict__ gwhh,
                    const float* __restrict__ gbih,  const float* __restrict__ gbhh,
                    float* __restrict__ out)
{
    const int tid  = threadIdx.x;
    const int lane = tid & 31;
    const int wid  = tid >> 5;
    const int gw   = blockIdx.x * (TPB/32) + wid;
    int ph = 0;

    __shared__ float sh_w[TPB/32];
    __shared__ float sh2[2][TPB/32];
    __shared__ float sh_a0, sh_a1, sh_inv;
    __shared__ __align__(16) float sh_rm[HD];

    // ---------- A1: partial column sums of h (per-block), plus d0 ----------
    {
        float acc0 = 0.f, acc1 = 0.f;
        const int c0 = tid, c1 = tid + TPB;
        for (int r = blockIdx.x; r < MQ + NP; r += GRID) {
            const float* row = (r < MQ) ? (h_q + r*D2) : (h_p + (size_t)(r - MQ)*D2);
            acc0 += row[c0];
            acc1 += row[c1];
        }
        g_hpart[blockIdx.x*D2 + c0] = acc0;
        g_hpart[blockIdx.x*D2 + c1] = acc1;
    }
    if (gw < 2*D2) {   // d0[i][j] = tanh(w_d_w[j] . src_i + b[j])
        const int i = gw >> 10, j = gw & (D2-1);
        const float4* src = (const float4*)(i == 0 ? h_q : h_p);  // row 0
        const float4* wr  = (const float4*)(w_d_w + (size_t)j*D2);
        float s = 0.f;
        for (int q = lane; q < D2/4; q += 32) { float4 a = wr[q], b = src[q]; FMA4(s, a, b); }
        s = wredsum(s);
        if (lane == 0) g_d[0][i*D2 + j] = tanhf(s + w_d_b[j]);
    }
    gsync(++ph);

    // ---------- A2: reduce partial column sums -> g_h ----------
    for (int j = blockIdx.x*TPB + tid; j < D2; j += NT) {
        float s = 0.f;
        for (int b = 0; b < GRID; b++) s += g_hpart[b*D2 + j];
        g_h[j] = s;
    }
    gsync(++ph);

    // ---------- A3: u_a_h = u_a_w @ h ----------
    if (gw < D2) {
        const float4* wr = (const float4*)(u_a_w + (size_t)gw*D2);
        const float4* hv = (const float4*)g_h;
        float s = 0.f;
        for (int q = lane; q < D2/4; q += 32) { float4 a = wr[q], b = hv[q]; FMA4(s, a, b); }
        s = wredsum(s);
        if (lane == 0) g_uah[gw] = s;
    }
    gsync(++ph);

    // =================== decode loop ===================
    int cur = 0;
    for (int t = 0; t < LL; ++t) {
        const float*  wt    = ans + (size_t)t*D2;       // E == D2
        const float4* wt4   = (const float4*)wt;
        const float*  dcur  = g_d[cur];
        const float4* dcur4 = (const float4*)dcur;
        float*        dnxt  = g_d[cur ^ 1];

        // ---- Phase 1: attention score partials s_i = sum_j v_w[j]*tanh(w_a_w[j].d_i + uah[j]) ----
        float p0 = 0.f, p1 = 0.f;
        if (gw < 2*D2) {
            const int i = gw >> 10, j = gw & (D2-1);
            const float4* wa = (const float4*)(w_a_w + (size_t)j*D2);
            const float4* dv = dcur4 + i*(D2/4);
            float s = 0.f;
            for (int q = lane; q < D2/4; q += 32) { float4 a = wa[q], b = dv[q]; FMA4(s, a, b); }
            s = wredsum(s);
            if (lane == 0) {
                float val = v_w[j] * tanhf(s + g_uah[j]);
                if (i == 0) p0 = val; else p1 = val;
            }
        }
        if (lane == 0) { sh2[0][wid] = p0; sh2[1][wid] = p1; }
        __syncthreads();
        if (tid == 0) {
            float s0 = 0.f, s1 = 0.f;
            for (int k = 0; k < TPB/32; k++) { s0 += sh2[0][k]; s1 += sh2[1][k]; }
            g_spart[blockIdx.x]        = s0;
            g_spart[GRID + blockIdx.x] = s1;
        }
        gsync(++ph);   // B1

        // every block: deterministic reduce of s, 2-way softmax -> (a0, a1)
        if (tid == 0) {
            float s0 = 0.f, s1 = 0.f;
            for (int b = 0; b < GRID; b++) { s0 += g_spart[b]; s1 += g_spart[GRID + b]; }
            float mx = fmaxf(s0, s1);
            float e0 = expf(s0 - mx), e1 = expf(s1 - mx);
            float inv = 1.f / (e0 + e1);
            sh_a0 = e0 * inv; sh_a1 = e1 * inv;
        }
        __syncthreads();
        const float a0 = sh_a0, a1 = sh_a1;

        // ---- Phase 3: fused GRU cell (c computed on-the-fly) ----
        if (gw < D4) {
            const int k = gw;
            const float4* Wih4 = (const float4*)gwih;
            const float4* Whh4 = (const float4*)gwhh;
            const int r0 = k*(D4/4), r1 = (k + D4)*(D4/4), r2 = (k + 2*D4)*(D4/4);
            float ir = 0.f, iz = 0.f, in_ = 0.f, hr = 0.f, hz = 0.f, hn = 0.f;
            for (int q = lane; q < D4/4; q += 32) {
                float4 xv;
                if (q < D2/4) xv = wt4[q];
                else {
                    float4 da = dcur4[q - D2/4], db = dcur4[q];
                    xv.x = a0*da.x + a1*db.x; xv.y = a0*da.y + a1*db.y;
                    xv.z = a0*da.z + a1*db.z; xv.w = a0*da.w + a1*db.w;
                }
                float4 hv = dcur4[q];
                float4 w0 = Wih4[r0 + q]; FMA4(ir,  w0, xv);
                float4 w1 = Wih4[r1 + q]; FMA4(iz,  w1, xv);
                float4 w2 = Wih4[r2 + q]; FMA4(in_, w2, xv);
                float4 v0 = Whh4[r0 + q]; FMA4(hr,  v0, hv);
                float4 v1 = Whh4[r1 + q]; FMA4(hz,  v1, hv);
                float4 v2 = Whh4[r2 + q]; FMA4(hn,  v2, hv);
            }
            float rr = wredsum(ir + hr);
            float zz = wredsum(iz + hz);
            in_ = wredsum(in_);
            hn  = wredsum(hn);
            if (lane == 0) {
                float r = 1.f / (1.f + expf(-(rr + gbih[k]      + gbhh[k])));
                float z = 1.f / (1.f + expf(-(zz + gbih[D4 + k] + gbhh[D4 + k])));
                float n = tanhf(in_ + gbih[2*D4 + k] + r * (hn + gbhh[2*D4 + k]));
                dnxt[k] = (1.f - z) * n + z * dcur[k];
            }
        }
        gsync(++ph);   // B2 (h_new complete)

        // ---- Phase 4: r_t projection + maxout (c on-the-fly again) ----
        if (gw < HD) {
            const int j = gw;
            const float4* wr0 = (const float4*)(w_r_w + (size_t)j*D2);
            const float4* wr1 = (const float4*)(w_r_w + (size_t)(j + HD)*D2);
            const float4* ur0 = (const float4*)(u_r_w + (size_t)j*D2);
            const float4* ur1 = (const float4*)(u_r_w + (size_t)(j + HD)*D2);
            const float4* vr0 = (const float4*)(v_r_w + (size_t)j*D4);
            const float4* vr1 = (const float4*)(v_r_w + (size_t)(j + HD)*D4);
            const float4* hn4 = (const float4*)dnxt;
            float A = 0.f, B = 0.f;
            for (int q = lane; q < D2/4; q += 32) {
                float4 wv = wt4[q];
                float4 da = dcur4[q], db = dcur4[q + D2/4];
                float4 cq;
                cq.x = a0*da.x + a1*db.x; cq.y = a0*da.y + a1*db.y;
                cq.z = a0*da.z + a1*db.z; cq.w = a0*da.w + a1*db.w;
                float4 pa = wr0[q]; FMA4(A, pa, wv);
                float4 pb = wr1[q]; FMA4(B, pb, wv);
                float4 ua = ur0[q]; FMA4(A, ua, cq);
                float4 ub = ur1[q]; FMA4(B, ub, cq);
            }
            for (int q = lane; q < D4/4; q += 32) {
                float4 hv = hn4[q];
                float4 va = vr0[q]; FMA4(A, va, hv);
                float4 vb = vr1[q]; FMA4(B, vb, hv);
            }
            A = wredsum(A); B = wredsum(B);
            if (lane == 0) g_rmax[j] = fmaxf(A, B);
        }
        gsync(++ph);   // B3 (rmax complete)

        // ---- Phase 5: vocab logits, exp (no max-subtract; logits are small), block partial sums ----
        for (int j = tid; j < HD; j += TPB) sh_rm[j] = g_rmax[j];
        __syncthreads();
        const float4* rm4 = (const float4*)sh_rm;
        float psum = 0.f;
        for (int v = gw; v < VV; v += NWARP) {
            const float4* wo = (const float4*)(w_o_w + (size_t)v*HD);
            float s = 0.f;
            for (int q = lane; q < HD/4; q += 32) { float4 a = wo[q], b = rm4[q]; FMA4(s, a, b); }
            s = wredsum(s);
            if (lane == 0) { float e = expf(s); g_elog[v] = e; psum += e; }
        }
        if (lane == 0) sh_w[wid] = psum;
        __syncthreads();
        if (tid == 0) {
            float s = 0.f;
            for (int k = 0; k < TPB/32; k++) s += sh_w[k];
            g_bsum[blockIdx.x] = s;
        }
        gsync(++ph);   // B4 (exp sums complete)

        // ---- Phase 6: normalize and emit probs row ----
        if (tid == 0) {
            float s = 0.f;
            for (int b = 0; b < GRID; b++) s += g_bsum[b];
            sh_inv = 1.f / s;
        }
        __syncthreads();
        const float inv = sh_inv;
        float* orow = out + (size_t)t*VV;
        for (int v = blockIdx.x*TPB + tid; v < VV; v += NT) orow[v] = g_elog[v] * inv;

        cur ^= 1;
    }
}

extern "C" void kernel_launch(void* const* d_in, const int* in_sizes, int n_in,
                              void* d_out, int out_size) {
    (void)in_sizes; (void)n_in; (void)out_size;
    init_bar_kernel<<<1, 1>>>();
    decoder_kernel<<<GRID, TPB>>>(
        (const float*)d_in[0],  (const float*)d_in[1],  (const float*)d_in[2],
        (const float*)d_in[3],  (const float*)d_in[4],  (const float*)d_in[5],
        (const float*)d_in[6],  (const float*)d_in[7],  (const float*)d_in[8],
        (const float*)d_in[9],  (const float*)d_in[10], (const float*)d_in[11],
        (const float*)d_in[12], (const float*)d_in[13], (const float*)d_in[14],
        (const float*)d_in[15], (float*)d_out);
}

// round 9
// speedup vs baseline: 1.5698x; 1.5698x over previous
#include <cuda_runtime.h>
#include <cuda_bf16.h>
#include <math.h>

#define GRID 148
#define TPB  512
#define NWPB (TPB/32)            /* 16 warps per block */
#define NWARP (GRID*NWPB)        /* 2368 */
#define NT    (GRID*TPB)         /* 75776 */

#define HD   512
#define D2   1024
#define D4   2048
#define VV   32000
#define MQ   32
#define NP   4096
#define LL   64

// ---------------- device scratch (no allocation allowed) ----------------
__device__ __align__(16) float g_h[D2];
__device__ __align__(16) float g_hpart[GRID*D2];
__device__ __align__(16) float g_uah[D2];
__device__ __align__(16) float g_d[2][D4];
__device__ __align__(16) float g_r1[D2];
__device__ __align__(16) float g_rmax[HD];
__device__ __align__(16) float g_elog[VV];
__device__ __align__(16) __nv_bfloat16 g_wo16[(size_t)VV*HD];   // 32.75 MB bf16 vocab weights
__device__ float g_spart2[2*GRID];
__device__ float g_bsum[GRID];
__device__ unsigned g_bar;

__global__ void init_bar_kernel() { g_bar = 0u; }

__device__ __forceinline__ float wredsum(float v) {
#pragma unroll
    for (int o = 16; o; o >>= 1) v += __shfl_xor_sync(0xffffffffu, v, o);
    return v;
}

// Grid barrier: release fence + arrive; poll with volatile load (no atomic
// contention); acquire fence (gpu scope -> L1 invalidate) on depart.
__device__ __forceinline__ void gsync(unsigned phase) {
    __syncthreads();
    if (threadIdx.x == 0) {
        __threadfence();
        atomicAdd(&g_bar, 1u);
        const unsigned target = (unsigned)GRID * phase;
        while (*((volatile unsigned*)&g_bar) < target) __nanosleep(32);
        __threadfence();
    }
    __syncthreads();
}

// deterministic 148-wide sum on warp 0 (all lanes return full sum)
__device__ __forceinline__ float red148(const float* __restrict__ p, int lane) {
    float s = 0.f;
#pragma unroll
    for (int i = 0; i < 5; i++) { int idx = lane + 32*i; if (idx < GRID) s += p[idx]; }
    return wredsum(s);
}

#define FMA4(acc, a, b) (acc) += (a).x*(b).x + (a).y*(b).y + (a).z*(b).z + (a).w*(b).w

__global__ __launch_bounds__(TPB, 1)
void decoder_kernel(const float* __restrict__ h_q,   const float* __restrict__ h_p,
                    const float* __restrict__ ans,   const float* __restrict__ v_w,
                    const float* __restrict__ w_d_w, const float* __restrict__ w_d_b,
                    const float* __restrict__ w_a_w, const float* __restrict__ u_a_w,
                    const float* __restrict__ w_r_w, const float* __restrict__ u_r_w,
                    const float* __restrict__ v_r_w, const float* __restrict__ w_o_w,
                    const float* __restrict__ gwih,  const float* __restrict__ gwhh,
                    const float* __restrict__ gbih,  const float* __restrict__ gbhh,
                    float* __restrict__ out)
{
    const int tid  = threadIdx.x;
    const int lane = tid & 31;
    const int wid  = tid >> 5;
    const int bid  = blockIdx.x;
    const int gw   = bid * NWPB + wid;
    unsigned ph = 0;

    __shared__ float sh_part[384];
    __shared__ float sh_ws[NWPB];
    __shared__ float sh_a0, sh_a1, sh_inv;
    __shared__ __align__(16) float sh_rm[HD];

    // per-block output counts (grid-stride by block over output indices)
    const int n_k = (bid < 124) ? 14 : 13;   // GRU outputs   (2048 = 13*148+124)
    const int n_j = (bid < 136) ? 7  : 6;    // r1 / w_a rows (1024 = 6*148+136)
    const int n_m = (bid < 68)  ? 4  : 3;    // maxout outs   (512  = 3*148+68)

    // ================= Prologue =================
    // P1: h column partial sums + d0 + w_o -> bf16 conversion
    {
        float acc0 = 0.f, acc1 = 0.f;
        const int c0 = tid, c1 = tid + TPB;
        for (int r = bid; r < MQ + NP; r += GRID) {
            const float* row = (r < MQ) ? (h_q + (size_t)r*D2) : (h_p + (size_t)(r - MQ)*D2);
            acc0 += row[c0];
            acc1 += row[c1];
        }
        g_hpart[bid*D2 + c0] = acc0;
        g_hpart[bid*D2 + c1] = acc1;
    }
    if (gw < 2*D2) {   // d0[i][j] = tanh(w_d_w[j] . src_i + b[j])
        const int i = gw >> 10, j = gw & (D2-1);
        const float4* src = (const float4*)(i == 0 ? h_q : h_p);
        const float4* wr  = (const float4*)(w_d_w + (size_t)j*D2);
        float s = 0.f;
        for (int q = lane; q < D2/4; q += 32) { float4 a = wr[q], b = src[q]; FMA4(s, a, b); }
        s = wredsum(s);
        if (lane == 0) g_d[0][i*D2 + j] = tanhf(s + w_d_b[j]);
    }
    for (int i = bid*TPB + tid; i < VV*HD/4; i += NT) {   // fp32 -> bf16
        float4 f = ((const float4*)w_o_w)[i];
        __nv_bfloat162 lo = __floats2bfloat162_rn(f.x, f.y);
        __nv_bfloat162 hi = __floats2bfloat162_rn(f.z, f.w);
        uint2 u; u.x = *(unsigned*)&lo; u.y = *(unsigned*)&hi;
        ((uint2*)g_wo16)[i] = u;
    }
    gsync(++ph);

    // P2: reduce column partials -> g_h
    for (int j = bid*TPB + tid; j < D2; j += NT) {
        float s = 0.f;
        for (int b = 0; b < GRID; b++) s += g_hpart[b*D2 + j];
        g_h[j] = s;
    }
    gsync(++ph);

    // P3: u_a_h = u_a_w @ h
    if (gw < D2) {
        const float4* wr = (const float4*)(u_a_w + (size_t)gw*D2);
        const float4* hv = (const float4*)g_h;
        float s = 0.f;
        for (int q = lane; q < D2/4; q += 32) { float4 a = wr[q], b = hv[q]; FMA4(s, a, b); }
        s = wredsum(s);
        if (lane == 0) g_uah[gw] = s;
    }
    gsync(++ph);

    // P4: attention score partials for d0 -> g_spart2
    {
        float s0p = 0.f, s1p = 0.f;
        if (gw < D2) {
            const int j = gw;
            const float4* wa  = (const float4*)(w_a_w + (size_t)j*D2);
            const float4* dlo = (const float4*)g_d[0];
            const float4* dhi = dlo + 256;
            float a = 0.f, b = 0.f;
            for (int q = lane; q < 256; q += 32) {
                float4 w4 = wa[q], x = dlo[q], y = dhi[q];
                FMA4(a, w4, x); FMA4(b, w4, y);
            }
            a = wredsum(a); b = wredsum(b);
            if (lane == 0) {
                float uv = g_uah[j], vw0 = v_w[j];
                s0p = vw0 * tanhf(a + uv);
                s1p = vw0 * tanhf(b + uv);
            }
        }
        if (lane == 0) { sh_part[wid] = s0p; sh_part[32 + wid] = s1p; }
        __syncthreads();
        if (tid == 0) {
            float A = 0.f, B = 0.f;
            for (int k = 0; k < NWPB; k++) { A += sh_part[k]; B += sh_part[32 + k]; }
            g_spart2[bid] = A; g_spart2[GRID + bid] = B;
        }
    }
    gsync(++ph);

    // ================= decode loop: 3 grid barriers / step =================
    int cur = 0;
    for (int t = 0; t < LL; ++t) {
        const float4* wt4   = (const float4*)(ans + (size_t)t*D2);
        const float*  dcur  = g_d[cur];
        const float4* dcur4 = (const float4*)dcur;
        float*        dnxt  = g_d[cur ^ 1];
        const float4* dnxt4 = (const float4*)dnxt;

        // a(t) from s-partials (warp-0 deterministic reduce, redundant per block)
        if (wid == 0) {
            float s0 = red148(g_spart2, lane);
            float s1 = red148(g_spart2 + GRID, lane);
            if (lane == 0) {
                float mx = fmaxf(s0, s1);
                float e0 = expf(s0 - mx), e1 = expf(s1 - mx);
                float inv = 1.f / (e0 + e1);
                sh_a0 = e0 * inv; sh_a1 = e1 * inv;
            }
        }
        __syncthreads();
        const float a0 = sh_a0, a1 = sh_a1;

        // ---- Segment A: GRU (all gates) + w_r@w + u_r@c, block-local tasks ----
        {
            const int totA = n_k*24 + n_j*4;
            for (int task = wid; task < totA; task += NWPB) {
                float s = 0.f;
                if (task < n_k*24) {
                    const int i = task / 24, sub = task - i*24;
                    const int g = sub >> 3, rem = sub & 7, src = rem >> 2, ch = rem & 3;
                    const int k = bid + i*GRID;
                    const float4* row4 = (const float4*)((src == 0 ? gwih : gwhh)
                                         + (size_t)(g*D4 + k) * D4);
                    const int q0 = ch*128 + lane;
                    if (src == 1) {
#pragma unroll
                        for (int it = 0; it < 4; it++) {
                            int q = q0 + 32*it; float4 w4 = row4[q], b = dcur4[q]; FMA4(s, w4, b);
                        }
                    } else if (ch < 2) {
#pragma unroll
                        for (int it = 0; it < 4; it++) {
                            int q = q0 + 32*it; float4 w4 = row4[q], b = wt4[q]; FMA4(s, w4, b);
                        }
                    } else {
#pragma unroll
                        for (int it = 0; it < 4; it++) {
                            int q = q0 + 32*it; float4 w4 = row4[q];
                            float4 da = dcur4[q - 256], db = dcur4[q], b;
                            b.x = a0*da.x + a1*db.x; b.y = a0*da.y + a1*db.y;
                            b.z = a0*da.z + a1*db.z; b.w = a0*da.w + a1*db.w;
                            FMA4(s, w4, b);
                        }
                    }
                } else {
                    const int u = task - n_k*24;
                    const int i = u >> 2, sub = u & 3, typ = sub >> 1, ch = sub & 1;
                    const int j = bid + i*GRID;
                    const int q0 = ch*128 + lane;
                    if (typ == 0) {
                        const float4* row4 = (const float4*)(w_r_w + (size_t)j*D2);
#pragma unroll
                        for (int it = 0; it < 4; it++) {
                            int q = q0 + 32*it; float4 w4 = row4[q], b = wt4[q]; FMA4(s, w4, b);
                        }
                    } else {
                        const float4* row4 = (const float4*)(u_r_w + (size_t)j*D2);
#pragma unroll
                        for (int it = 0; it < 4; it++) {
                            int q = q0 + 32*it; float4 w4 = row4[q];
                            float4 da = dcur4[q], db = dcur4[q + 256], b;
                            b.x = a0*da.x + a1*db.x; b.y = a0*da.y + a1*db.y;
                            b.z = a0*da.z + a1*db.z; b.w = a0*da.w + a1*db.w;
                            FMA4(s, w4, b);
                        }
                    }
                }
                s = wredsum(s);
                if (lane == 0) sh_part[task] = s;
            }
            __syncthreads();
            if (tid < n_k) {                      // fixed-order GRU combine
                const int k = bid + tid*GRID;
                const float* p = sh_part + tid*24;
                float i0 = p[0]+p[1]+p[2]+p[3],    h0 = p[4]+p[5]+p[6]+p[7];
                float i1 = p[8]+p[9]+p[10]+p[11],  h1 = p[12]+p[13]+p[14]+p[15];
                float i2 = p[16]+p[17]+p[18]+p[19],h2 = p[20]+p[21]+p[22]+p[23];
                float r = 1.f / (1.f + expf(-(i0 + h0 + gbih[k]        + gbhh[k])));
                float z = 1.f / (1.f + expf(-(i1 + h1 + gbih[D4 + k]   + gbhh[D4 + k])));
                float n = tanhf(i2 + gbih[2*D4 + k] + r * (h2 + gbhh[2*D4 + k]));
                dnxt[k] = (1.f - z) * n + z * dcur[k];
            } else if (tid >= 64 && tid < 64 + n_j) {
                const int i = tid - 64, j = bid + i*GRID;
                const float* p = sh_part + n_k*24 + i*4;
                g_r1[j] = p[0] + p[1] + p[2] + p[3];
            }
        }
        gsync(++ph);   // alpha: h_new, r1 ready

        // ---- Segment B: v_r@h_new + maxout, and attention scores for t+1 ----
        {
            const int totB = n_m*8 + n_j*2;
            for (int task = wid; task < totB; task += NWPB) {
                if (task < n_m*8) {
                    const int i = task >> 3, sub = task & 7, half = sub >> 2, ch = sub & 3;
                    const int j = bid + i*GRID;
                    const float4* row4 = (const float4*)(v_r_w + (size_t)(j + half*HD)*D4);
                    const int q0 = ch*128 + lane;
                    float s = 0.f;
#pragma unroll
                    for (int it = 0; it < 4; it++) {
                        int q = q0 + 32*it; float4 w4 = row4[q], b = dnxt4[q]; FMA4(s, w4, b);
                    }
                    s = wredsum(s);
                    if (lane == 0) sh_part[task] = s;
                } else {
                    const int u = task - n_m*8;
                    const int i = u >> 1, ch = u & 1;
                    const int jr = bid + i*GRID;
                    const float4* row4 = (const float4*)(w_a_w + (size_t)jr*D2);
                    const int q0 = ch*128 + lane;
                    float sa = 0.f, sb = 0.f;
#pragma unroll
                    for (int it = 0; it < 4; it++) {
                        int q = q0 + 32*it; float4 w4 = row4[q];
                        float4 x = dnxt4[q], y = dnxt4[q + 256];
                        FMA4(sa, w4, x); FMA4(sb, w4, y);
                    }
                    sa = wredsum(sa); sb = wredsum(sb);
                    if (lane == 0) { sh_part[64 + u] = sa; sh_part[96 + u] = sb; }
                }
            }
            __syncthreads();
            if (tid < n_j) {                      // per-row tanh for s(t+1)
                const int jr = bid + tid*GRID;
                float uv = g_uah[jr], vw0 = v_w[jr];
                float t0 = sh_part[64 + tid*2] + sh_part[64 + tid*2 + 1];
                float t1 = sh_part[96 + tid*2] + sh_part[96 + tid*2 + 1];
                sh_part[128 + tid] = vw0 * tanhf(t0 + uv);
                sh_part[160 + tid] = vw0 * tanhf(t1 + uv);
            } else if (tid >= 32 && tid < 32 + n_m) {
                const int i = tid - 32, j = bid + i*GRID;
                const float* p = sh_part + i*8;
                float A = g_r1[j]      + p[0] + p[1] + p[2] + p[3];
                float B = g_r1[j + HD] + p[4] + p[5] + p[6] + p[7];
                g_rmax[j] = fmaxf(A, B);
            }
            __syncthreads();
            if (tid == 0) {
                float A = 0.f, B = 0.f;
                for (int i = 0; i < n_j; i++) { A += sh_part[128 + i]; B += sh_part[160 + i]; }
                g_spart2[bid] = A; g_spart2[GRID + bid] = B;
            }
        }
        gsync(++ph);   // beta: rmax, s-partials ready

        // ---- Segment C: vocab logits (bf16) + exp + block partial sums ----
        {
            for (int v = tid; v < HD; v += TPB) sh_rm[v] = g_rmax[v];
            __syncthreads();
            // hoist this lane's rmax slice (same for every vocab row)
            float4 ra0 = *(const float4*)(sh_rm + lane*8);
            float4 ra1 = *(const float4*)(sh_rm + lane*8 + 4);
            float4 rb0 = *(const float4*)(sh_rm + (lane + 32)*8);
            float4 rb1 = *(const float4*)(sh_rm + (lane + 32)*8 + 4);
            float psum = 0.f;
            for (int v = gw; v < VV; v += NWARP) {
                const uint4* wo4 = (const uint4*)(g_wo16 + (size_t)v*HD);
                uint4 ua = wo4[lane];
                uint4 ub = wo4[lane + 32];
                float s = 0.f;
                {
                    float2 f0 = __bfloat1622float2(*(__nv_bfloat162*)&ua.x);
                    float2 f1 = __bfloat1622float2(*(__nv_bfloat162*)&ua.y);
                    float2 f2 = __bfloat1622float2(*(__nv_bfloat162*)&ua.z);
                    float2 f3 = __bfloat1622float2(*(__nv_bfloat162*)&ua.w);
                    s += f0.x*ra0.x + f0.y*ra0.y + f1.x*ra0.z + f1.y*ra0.w
                       + f2.x*ra1.x + f2.y*ra1.y + f3.x*ra1.z + f3.y*ra1.w;
                }
                {
                    float2 f0 = __bfloat1622float2(*(__nv_bfloat162*)&ub.x);
                    float2 f1 = __bfloat1622float2(*(__nv_bfloat162*)&ub.y);
                    float2 f2 = __bfloat1622float2(*(__nv_bfloat162*)&ub.z);
                    float2 f3 = __bfloat1622float2(*(__nv_bfloat162*)&ub.w);
                    s += f0.x*rb0.x + f0.y*rb0.y + f1.x*rb0.z + f1.y*rb0.w
                       + f2.x*rb1.x + f2.y*rb1.y + f3.x*rb1.z + f3.y*rb1.w;
                }
                s = wredsum(s);
                if (lane == 0) { float e = expf(s); g_elog[v] = e; psum += e; }
            }
            if (lane == 0) sh_ws[wid] = psum;
            __syncthreads();
            if (tid == 0) {
                float s = 0.f;
                for (int k = 0; k < NWPB; k++) s += sh_ws[k];
                g_bsum[bid] = s;
            }
        }
        gsync(++ph);   // gamma: exp sums ready

        // ---- Segment D: normalize + emit (no trailing barrier needed) ----
        if (wid == 0) {
            float s = red148(g_bsum, lane);
            if (lane == 0) sh_inv = 1.f / s;
        }
        __syncthreads();
        const float inv = sh_inv;
        float* orow = out + (size_t)t*VV;
        for (int v = bid*TPB + tid; v < VV; v += NT) orow[v] = g_elog[v] * inv;

        cur ^= 1;
    }
}

extern "C" void kernel_launch(void* const* d_in, const int* in_sizes, int n_in,
                              void* d_out, int out_size) {
    (void)in_sizes; (void)n_in; (void)out_size;
    init_bar_kernel<<<1, 1>>>();
    decoder_kernel<<<GRID, TPB>>>(
        (const float*)d_in[0],  (const float*)d_in[1],  (const float*)d_in[2],
        (const float*)d_in[3],  (const float*)d_in[4],  (const float*)d_in[5],
        (const float*)d_in[6],  (const float*)d_in[7],  (const float*)d_in[8],
        (const float*)d_in[9],  (const float*)d_in[10], (const float*)d_in[11],
        (const float*)d_in[12], (const float*)d_in[13], (const float*)d_in[14],
        (const float*)d_in[15], (float*)d_out);
}